// round 16
// baseline (speedup 1.0000x reference)
#include <cuda_runtime.h>
#include <cuda_fp16.h>
#include <cstdint>
#include <cstddef>

// ---------------------------------------------------------------------------
// GatedGraphConv (10 layers) + GRUCell.
//  - Algebra: segment_sum linear => gi = aggH @ (w_ih@W_l^T)^T + b_ih
//  - fp16 2-term split: activations A = Ah + Al (both fp16), weights single
//    fp16. A@B ~= Ah@B + Al@B  (residual = weight rounding ~2^-12).
//  - r/z gates: K=256 concat GEMM  [agg|h] @ [B_g|W_g]^T  (dual-accumulate).
//  - Per layer: CSR gather kernel (4-way unrolled), then ONE fused GEMM+GRU.
// ---------------------------------------------------------------------------

#define C_DIM 128
#define N_MAX 100352
#define E_MAX 1048576
#define L_MAX 16
#define WCAT_PER_L 98304   // 2*128*256 (r,z concat) + 2*128*128 (in, hn)

__device__ __align__(128) float g_h  [(size_t)N_MAX * C_DIM];
__device__ __align__(128) float g_agg[(size_t)N_MAX * C_DIM];
__device__ __align__(128) float g_bl [(size_t)L_MAX * 3 * C_DIM * C_DIM];
__device__ __align__(128) __half g_wcat[(size_t)L_MAX * WCAT_PER_L];
__device__ __align__(128) int g_src[E_MAX];
__device__ __align__(128) int g_dst[E_MAX];
__device__ __align__(128) int g_sorted_src[E_MAX];
__device__ __align__(128) int g_deg    [N_MAX];
__device__ __align__(128) int g_partial[N_MAX];
__device__ __align__(128) int g_rowptr [N_MAX + 1];
__device__ __align__(128) int g_cursor [N_MAX];
__device__ __align__(128) int g_bsums  [256];
__device__ int g_is64;

// ============================ helpers ======================================
__device__ __forceinline__ uint32_t smem_u32(const void* p) {
    uint32_t a;
    asm("{ .reg .u64 t; cvta.to.shared.u64 t, %1; cvt.u32.u64 %0, t; }" : "=r"(a) : "l"(p));
    return a;
}
__device__ __forceinline__ void ldmatrix_x4(uint32_t& r0, uint32_t& r1,
                                            uint32_t& r2, uint32_t& r3, uint32_t addr) {
    asm volatile("ldmatrix.sync.aligned.m8n8.x4.shared.b16 {%0,%1,%2,%3}, [%4];"
                 : "=r"(r0), "=r"(r1), "=r"(r2), "=r"(r3) : "r"(addr));
}
__device__ __forceinline__ void mma_fp16(float* d, const uint32_t* a, const uint32_t* b) {
    asm volatile(
        "mma.sync.aligned.m16n8k16.row.col.f32.f16.f16.f32 "
        "{%0,%1,%2,%3}, {%4,%5,%6,%7}, {%8,%9}, {%0,%1,%2,%3};"
        : "+f"(d[0]), "+f"(d[1]), "+f"(d[2]), "+f"(d[3])
        : "r"(a[0]), "r"(a[1]), "r"(a[2]), "r"(a[3]), "r"(b[0]), "r"(b[1]));
}
__device__ __forceinline__ float sigmoidf_(float x) { return 1.f / (1.f + __expf(-x)); }

// split float4 -> packed fp16 hi x4 and fp16 lo x4
__device__ __forceinline__ void split4h(float4 v, uint2& hi, uint2& lo) {
    __half hx = __float2half_rn(v.x), hy = __float2half_rn(v.y);
    __half hz = __float2half_rn(v.z), hw = __float2half_rn(v.w);
    __half ox = __float2half_rn(v.x - __half2float(hx));
    __half oy = __float2half_rn(v.y - __half2float(hy));
    __half oz = __float2half_rn(v.z - __half2float(hz));
    __half ow = __float2half_rn(v.w - __half2float(hw));
    hi.x = (uint32_t)__half_as_ushort(hx) | ((uint32_t)__half_as_ushort(hy) << 16);
    hi.y = (uint32_t)__half_as_ushort(hz) | ((uint32_t)__half_as_ushort(hw) << 16);
    lo.x = (uint32_t)__half_as_ushort(ox) | ((uint32_t)__half_as_ushort(oy) << 16);
    lo.y = (uint32_t)__half_as_ushort(oz) | ((uint32_t)__half_as_ushort(ow) << 16);
}

// ============================ prologue kernels =============================
__global__ void detect_edge_dtype_kernel(const int* __restrict__ e32, int nscan) {
    if (threadIdx.x == 0 && blockIdx.x == 0) {
        int acc = 0;
        for (int i = 1; i < nscan; i += 2) acc |= e32[i];
        g_is64 = (acc == 0) ? 1 : 0;
    }
}
__global__ void decode_edges_kernel(const int* __restrict__ e32, int E) {
    int i = blockIdx.x * blockDim.x + threadIdx.x;
    if (i >= E) return;
    if (g_is64) { g_src[i] = e32[2 * (size_t)i]; g_dst[i] = e32[2 * ((size_t)E + i)]; }
    else        { g_src[i] = e32[i];             g_dst[i] = e32[(size_t)E + i]; }
}
__global__ void copy_f4_kernel(const float4* __restrict__ s, float4* __restrict__ d, int n4) {
    int i = blockIdx.x * blockDim.x + threadIdx.x;
    if (i < n4) d[i] = s[i];
}

// wcat per layer: [0,65536): g in {r,z}: [c][k] k<128 -> Bl[g*128+c][k] else whh
//                 [65536,81920): in rows ; [81920,98304): hn rows
__global__ void build_wcat_kernel(const float* __restrict__ bl,
                                  const float* __restrict__ whh, int total) {
    int i = blockIdx.x * blockDim.x + threadIdx.x;
    if (i >= total) return;
    int l = i / WCAT_PER_L;
    int r = i - l * WCAT_PER_L;
    float v;
    if (r < 65536) {
        int g = r >> 15, rem = r & 32767, c = rem >> 8, k = rem & 255;
        int row = g * 128 + c;
        v = (k < 128) ? bl[(size_t)l * 49152 + row * 128 + k]
                      : whh[row * 128 + (k - 128)];
    } else {
        int r2 = r - 65536;
        int m = r2 >> 14, rem = r2 & 16383, c = rem >> 7, k = rem & 127;
        int row = 256 + c;
        v = m ? whh[row * 128 + k] : bl[(size_t)l * 49152 + row * 128 + k];
    }
    g_wcat[i] = __float2half_rn(v);
}

// ---- CSR build (once per call) ----
__global__ void zero_int_kernel(int* __restrict__ p, int n) {
    int i = blockIdx.x * blockDim.x + threadIdx.x;
    if (i < n) p[i] = 0;
}
__global__ void hist_kernel(int E) {
    int i = blockIdx.x * blockDim.x + threadIdx.x;
    if (i < E) atomicAdd(&g_deg[g_dst[i]], 1);
}
#define SCAN_BLK 1024
__global__ void scan_block_kernel(int N) {
    __shared__ int sh[SCAN_BLK];
    int tid = threadIdx.x;
    int gid = blockIdx.x * SCAN_BLK + tid;
    int v = (gid < N) ? g_deg[gid] : 0;
    sh[tid] = v; __syncthreads();
    for (int off = 1; off < SCAN_BLK; off <<= 1) {
        int t = (tid >= off) ? sh[tid - off] : 0;
        __syncthreads();
        sh[tid] += t;
        __syncthreads();
    }
    if (gid < N) g_partial[gid] = sh[tid] - v;
    if (tid == SCAN_BLK - 1) g_bsums[blockIdx.x] = sh[tid];
}
// parallel exclusive scan over block sums (nb <= 256)
__global__ void scan_sums_kernel(int nb) {
    __shared__ int sh[256];
    int tid = threadIdx.x;
    int v = (tid < nb) ? g_bsums[tid] : 0;
    sh[tid] = v; __syncthreads();
    for (int off = 1; off < 256; off <<= 1) {
        int t = (tid >= off) ? sh[tid - off] : 0;
        __syncthreads();
        sh[tid] += t;
        __syncthreads();
    }
    if (tid < nb) g_bsums[tid] = sh[tid] - v;
}
__global__ void scan_add_kernel(int N, int E) {
    int gid = blockIdx.x * blockDim.x + threadIdx.x;
    if (gid < N) {
        int v = g_partial[gid] + g_bsums[gid / SCAN_BLK];
        g_rowptr[gid] = v;
        g_cursor[gid] = v;
    }
    if (gid == N) g_rowptr[N] = E;
}
__global__ void csr_fill_kernel(int E) {
    int i = blockIdx.x * blockDim.x + threadIdx.x;
    if (i >= E) return;
    int pos = atomicAdd(&g_cursor[g_dst[i]], 1);
    g_sorted_src[pos] = g_src[i];
}

// ---- per-layer aggregation: warp per node, 4-way unrolled for MLP ----
__global__ void aggregate_csr_kernel(const float* __restrict__ h,
                                     float* __restrict__ agg, int N)
{
    int t = blockIdx.x * blockDim.x + threadIdx.x;
    int node = t >> 5, lane = t & 31;
    if (node >= N) return;
    int e0 = g_rowptr[node], e1 = g_rowptr[node + 1];
    float4 a0 = make_float4(0.f, 0.f, 0.f, 0.f);
    float4 a1 = make_float4(0.f, 0.f, 0.f, 0.f);
    float4 a2 = make_float4(0.f, 0.f, 0.f, 0.f);
    float4 a3 = make_float4(0.f, 0.f, 0.f, 0.f);
    int e = e0;
    for (; e + 4 <= e1; e += 4) {
        int s0 = g_sorted_src[e];
        int s1 = g_sorted_src[e + 1];
        int s2 = g_sorted_src[e + 2];
        int s3 = g_sorted_src[e + 3];
        float4 v0 = __ldg(reinterpret_cast<const float4*>(h + (size_t)s0 * C_DIM) + lane);
        float4 v1 = __ldg(reinterpret_cast<const float4*>(h + (size_t)s1 * C_DIM) + lane);
        float4 v2 = __ldg(reinterpret_cast<const float4*>(h + (size_t)s2 * C_DIM) + lane);
        float4 v3 = __ldg(reinterpret_cast<const float4*>(h + (size_t)s3 * C_DIM) + lane);
        a0.x += v0.x; a0.y += v0.y; a0.z += v0.z; a0.w += v0.w;
        a1.x += v1.x; a1.y += v1.y; a1.z += v1.z; a1.w += v1.w;
        a2.x += v2.x; a2.y += v2.y; a2.z += v2.z; a2.w += v2.w;
        a3.x += v3.x; a3.y += v3.y; a3.z += v3.z; a3.w += v3.w;
    }
    if (e + 2 <= e1) {
        int s0 = g_sorted_src[e];
        int s1 = g_sorted_src[e + 1];
        float4 v0 = __ldg(reinterpret_cast<const float4*>(h + (size_t)s0 * C_DIM) + lane);
        float4 v1 = __ldg(reinterpret_cast<const float4*>(h + (size_t)s1 * C_DIM) + lane);
        a0.x += v0.x; a0.y += v0.y; a0.z += v0.z; a0.w += v0.w;
        a1.x += v1.x; a1.y += v1.y; a1.z += v1.z; a1.w += v1.w;
        e += 2;
    }
    if (e < e1) {
        int s0 = g_sorted_src[e];
        float4 v0 = __ldg(reinterpret_cast<const float4*>(h + (size_t)s0 * C_DIM) + lane);
        a0.x += v0.x; a0.y += v0.y; a0.z += v0.z; a0.w += v0.w;
    }
    a0.x += a1.x; a0.y += a1.y; a0.z += a1.z; a0.w += a1.w;
    a2.x += a3.x; a2.y += a3.y; a2.z += a3.z; a2.w += a3.w;
    a0.x += a2.x; a0.y += a2.y; a0.z += a2.z; a0.w += a2.w;
    *(reinterpret_cast<float4*>(agg + (size_t)node * C_DIM) + lane) = a0;
}

// ================= SIMT NT GEMM (tiny B_l precompute, batched over z) ======
__global__ void __launch_bounds__(256) gemm_nt_batched_kernel(
    const float* __restrict__ A, const float* __restrict__ Wall,
    float* __restrict__ CoutAll, int M, int nout)
{
    __shared__ float As[64][68];
    __shared__ float Bs[64][68];
    const float* B = Wall + (size_t)blockIdx.z * C_DIM * C_DIM;
    float* Cout = CoutAll + (size_t)blockIdx.z * 3 * C_DIM * C_DIM;
    const int tid = threadIdx.x;
    const int row0 = blockIdx.x * 64, col0 = blockIdx.y * 64;
    const int tx = tid & 15, ty = tid >> 4;
    float acc[4][4];
#pragma unroll
    for (int i = 0; i < 4; i++)
#pragma unroll
        for (int j = 0; j < 4; j++) acc[i][j] = 0.f;
#pragma unroll
    for (int kt = 0; kt < 2; kt++) {
#pragma unroll
        for (int s = 0; s < 4; s++) {
            int i = tid + s * 256, r = i >> 4, c4 = i & 15;
            float4 va = make_float4(0.f, 0.f, 0.f, 0.f);
            if (row0 + r < M)
                va = *reinterpret_cast<const float4*>(A + (size_t)(row0 + r) * C_DIM + kt * 64 + c4 * 4);
            *reinterpret_cast<float4*>(&As[r][c4 * 4]) = va;
            float4 vb = *reinterpret_cast<const float4*>(B + (size_t)(col0 + r) * C_DIM + kt * 64 + c4 * 4);
            *reinterpret_cast<float4*>(&Bs[r][c4 * 4]) = vb;
        }
        __syncthreads();
#pragma unroll
        for (int k4 = 0; k4 < 16; k4++) {
            float4 a[4], b[4];
#pragma unroll
            for (int i = 0; i < 4; i++) a[i] = *reinterpret_cast<const float4*>(&As[ty * 4 + i][k4 * 4]);
#pragma unroll
            for (int j = 0; j < 4; j++) b[j] = *reinterpret_cast<const float4*>(&Bs[tx * 4 + j][k4 * 4]);
#pragma unroll
            for (int i = 0; i < 4; i++)
#pragma unroll
                for (int j = 0; j < 4; j++) {
                    acc[i][j] += a[i].x * b[j].x; acc[i][j] += a[i].y * b[j].y;
                    acc[i][j] += a[i].z * b[j].z; acc[i][j] += a[i].w * b[j].w;
                }
        }
        __syncthreads();
    }
#pragma unroll
    for (int i = 0; i < 4; i++) {
        int r = row0 + ty * 4 + i;
        if (r < M)
#pragma unroll
            for (int j = 0; j < 4; j++)
                Cout[(size_t)r * nout + col0 + tx * 4 + j] = acc[i][j];
    }
}

// ================== fused layer kernel (GEMMs + GRU) =======================
// EXACT R13 structure (best measured). CTA: 64 rows. A tile = [agg | h]
// 64 x 256 fp16, hi + lo. Phases: r (K=256), z (K=256), n (in+hn K=128 pair).
#define A_LDA 528                       // 256 fp16 * 2 + 16B pad
#define A_TILE (64 * A_LDA)             // 33792
#define B_LDA_RZ 528
#define B_LDA_N  272
#define SM_AHI 0
#define SM_ALO A_TILE
#define SM_B   (2 * A_TILE)             // 67584
#define SM_TOT (2 * A_TILE + 69632)     // 137216

__device__ __forceinline__ void phase2(uint32_t aH0, uint32_t aL0, uint32_t bB0,
                                       const int bstride, const int ksteps,
                                       float acc[2][2][4])
{
#pragma unroll
    for (int ks = 0; ks < ksteps; ks++) {
        const uint32_t koff = ks * 32;
        uint32_t aH[2][4], aL[2][4], bH[4];
#pragma unroll
        for (int im = 0; im < 2; im++) {
            ldmatrix_x4(aH[im][0], aH[im][1], aH[im][2], aH[im][3],
                        aH0 + (uint32_t)im * 16 * A_LDA + koff);
            ldmatrix_x4(aL[im][0], aL[im][1], aL[im][2], aL[im][3],
                        aL0 + (uint32_t)im * 16 * A_LDA + koff);
        }
        ldmatrix_x4(bH[0], bH[1], bH[2], bH[3], bB0 + koff);
#pragma unroll
        for (int im = 0; im < 2; im++)
#pragma unroll
            for (int in = 0; in < 2; in++) {
                mma_fp16(acc[im][in], aH[im], &bH[in * 2]);
                mma_fp16(acc[im][in], aL[im], &bH[in * 2]);
            }
    }
}

__global__ void __launch_bounds__(512, 1)
fused_layer_kernel(const float* __restrict__ agg, float* __restrict__ h,
                   const __half* __restrict__ wl,
                   const float* __restrict__ b_ih, const float* __restrict__ b_hh,
                   float* __restrict__ out_relu, int M)
{
    extern __shared__ char smem[];
    const int tid  = threadIdx.x;
    const int wid  = tid >> 5;
    const int lane = tid & 31;
    const int row0 = blockIdx.x * 64;
    const int wm = wid & 1;
    const int wn = wid >> 1;

    // ---- build A tile: [agg | h] rows, fp16 hi/lo split ----
#pragma unroll
    for (int it = 0; it < 8; it++) {
        int idx = tid + it * 512;           // 0..4095 float4 over 64x256
        int row = idx >> 6;                 // 0..63
        int kk  = (idx & 63) * 4;           // 0..252
        bool ok = (row0 + row < M);
        float4 v = make_float4(0.f, 0.f, 0.f, 0.f);
        if (ok) {
            const float* srcp = (kk < 128)
                ? (agg + (size_t)(row0 + row) * C_DIM + kk)
                : (h   + (size_t)(row0 + row) * C_DIM + (kk - 128));
            v = *reinterpret_cast<const float4*>(srcp);
        }
        uint2 hi, lo;
        split4h(v, hi, lo);
        uint32_t off = (uint32_t)row * A_LDA + kk * 2;
        *reinterpret_cast<uint2*>(smem + SM_AHI + off) = hi;
        *reinterpret_cast<uint2*>(smem + SM_ALO + off) = lo;
    }

    // ---- fragment addressing ----
    const uint32_t sb = smem_u32(smem);
    const uint32_t a_off =
        (uint32_t)(wm * 32 + (lane & 15)) * A_LDA + (uint32_t)(lane >> 4) * 16;
    const uint32_t aH0 = sb + SM_AHI + a_off;
    const uint32_t aL0 = sb + SM_ALO + a_off;
    const uint32_t b_row = (uint32_t)(wn * 16 + ((lane >> 4) & 1) * 8 + (lane & 7));
    const uint32_t b_col = (uint32_t)((lane >> 3) & 1) * 16;
    const uint32_t bRZ = sb + SM_B + b_row * B_LDA_RZ + b_col;
    const uint32_t bN  = sb + SM_B + b_row * B_LDA_N  + b_col;

    float acc_r [2][2][4], acc_z [2][2][4], acc_in[2][2][4], acc_hn[2][2][4];
#pragma unroll
    for (int im = 0; im < 2; im++)
#pragma unroll
        for (int in = 0; in < 2; in++)
#pragma unroll
            for (int q = 0; q < 4; q++) {
                acc_r[im][in][q] = 0.f; acc_z[im][in][q] = 0.f;
                acc_in[im][in][q] = 0.f; acc_hn[im][in][q] = 0.f;
            }

    // ---- phase r: load wcat_rz[0] (128 x 256 fp16), K=256 ----
#pragma unroll
    for (int it = 0; it < 8; it++) {
        int idx = tid + it * 512;           // 0..4095 uint4
        int r = idx >> 5, c4 = idx & 31;
        uint4 v = *reinterpret_cast<const uint4*>(wl + (size_t)r * 256 + c4 * 8);
        *reinterpret_cast<uint4*>(smem + SM_B + (uint32_t)r * B_LDA_RZ + c4 * 16) = v;
    }
    __syncthreads();
    phase2(aH0, aL0, bRZ, B_LDA_RZ, 16, acc_r);
    __syncthreads();

    // ---- phase z: load wcat_rz[1], K=256 ----
#pragma unroll
    for (int it = 0; it < 8; it++) {
        int idx = tid + it * 512;
        int r = idx >> 5, c4 = idx & 31;
        uint4 v = *reinterpret_cast<const uint4*>(wl + 32768 + (size_t)r * 256 + c4 * 8);
        *reinterpret_cast<uint4*>(smem + SM_B + (uint32_t)r * B_LDA_RZ + c4 * 16) = v;
    }
    __syncthreads();
    phase2(aH0, aL0, bRZ, B_LDA_RZ, 16, acc_z);
    __syncthreads();

    // ---- phase n: load in (128x128) + hn (128x128) together ----
#pragma unroll
    for (int it = 0; it < 8; it++) {
        int idx = tid + it * 512;           // 0..4095
        int m = idx >> 11, rem = idx & 2047;
        int r = rem >> 4, c4 = rem & 15;
        uint4 v = *reinterpret_cast<const uint4*>(wl + 65536 + m * 16384 + (size_t)r * 128 + c4 * 8);
        *reinterpret_cast<uint4*>(smem + SM_B + m * 34816 + (uint32_t)r * B_LDA_N + c4 * 16) = v;
    }
    __syncthreads();
    phase2(aH0,       aL0,       bN,         B_LDA_N, 8, acc_in);   // agg half (K cols 0-127)
    phase2(aH0 + 256, aL0 + 256, bN + 34816, B_LDA_N, 8, acc_hn);   // h half  (K cols 128-255)

    // ---- epilogue: GRU, in-place h update ----
    const int row_l = lane >> 2;
    const int col_l = (lane & 3) * 2;
#pragma unroll
    for (int in = 0; in < 2; in++) {
        const int c = wn * 16 + in * 8 + col_l;
        const float bir0 = __ldg(b_ih + c),       bir1 = __ldg(b_ih + c + 1);
        const float bhr0 = __ldg(b_hh + c),       bhr1 = __ldg(b_hh + c + 1);
        const float biz0 = __ldg(b_ih + 128 + c), biz1 = __ldg(b_ih + 129 + c);
        const float bhz0 = __ldg(b_hh + 128 + c), bhz1 = __ldg(b_hh + 129 + c);
        const float bin0 = __ldg(b_ih + 256 + c), bin1 = __ldg(b_ih + 257 + c);
        const float bhn0 = __ldg(b_hh + 256 + c), bhn1 = __ldg(b_hh + 257 + c);
#pragma unroll
        for (int im = 0; im < 2; im++) {
#pragma unroll
            for (int q = 0; q < 2; q++) {
                int r = row0 + wm * 32 + im * 16 + q * 8 + row_l;
                if (r >= M) continue;
                float2 hold = *reinterpret_cast<const float2*>(h + (size_t)r * C_DIM + c);
                float rr0 = sigmoidf_(acc_r[im][in][q * 2 + 0] + bir0 + bhr0);
                float rr1 = sigmoidf_(acc_r[im][in][q * 2 + 1] + bir1 + bhr1);
                float zz0 = sigmoidf_(acc_z[im][in][q * 2 + 0] + biz0 + bhz0);
                float zz1 = sigmoidf_(acc_z[im][in][q * 2 + 1] + biz1 + bhz1);
                float nn0 = tanhf(acc_in[im][in][q * 2 + 0] + bin0 + rr0 * (acc_hn[im][in][q * 2 + 0] + bhn0));
                float nn1 = tanhf(acc_in[im][in][q * 2 + 1] + bin1 + rr1 * (acc_hn[im][in][q * 2 + 1] + bhn1));
                float h0 = (1.f - zz0) * nn0 + zz0 * hold.x;
                float h1 = (1.f - zz1) * nn1 + zz1 * hold.y;
                *reinterpret_cast<float2*>(h + (size_t)r * C_DIM + c) = make_float2(h0, h1);
                if (out_relu)
                    *reinterpret_cast<float2*>(out_relu + (size_t)r * C_DIM + c) =
                        make_float2(fmaxf(h0, 0.f), fmaxf(h1, 0.f));
            }
        }
    }
}

// ============================ launch =======================================
extern "C" void kernel_launch(void* const* d_in, const int* in_sizes, int n_in,
                              void* d_out, int out_size)
{
    const float* x    = (const float*)d_in[0];
    const int*   e32  = (const int*)  d_in[1];
    const float* w    = (const float*)d_in[2];
    const float* w_ih = (const float*)d_in[3];
    const float* w_hh = (const float*)d_in[4];
    const float* b_ih = (const float*)d_in[5];
    const float* b_hh = (const float*)d_in[6];

    const int N = in_sizes[0] / C_DIM;
    const int E = in_sizes[1] / 2;
    const int L = in_sizes[2] / (C_DIM * C_DIM);

    float *p_h, *p_agg, *p_bl;
    __half *p_wcat;
    cudaGetSymbolAddress((void**)&p_h,    g_h);
    cudaGetSymbolAddress((void**)&p_agg,  g_agg);
    cudaGetSymbolAddress((void**)&p_bl,   g_bl);
    cudaGetSymbolAddress((void**)&p_wcat, g_wcat);
    int *p_deg;
    cudaGetSymbolAddress((void**)&p_deg, g_deg);

    cudaFuncSetAttribute(fused_layer_kernel,
                         cudaFuncAttributeMaxDynamicSharedMemorySize, SM_TOT);

    // ---- edges + CSR (once) ----
    int nscan = 1024;
    if (2 * E < nscan) nscan = 2 * E;
    detect_edge_dtype_kernel<<<1, 32>>>(e32, nscan);
    decode_edges_kernel<<<(E + 255) / 256, 256>>>(e32, E);
    zero_int_kernel<<<(N + 255) / 256, 256>>>(p_deg, N);
    hist_kernel<<<(E + 255) / 256, 256>>>(E);
    const int nb = (N + SCAN_BLK - 1) / SCAN_BLK;
    scan_block_kernel<<<nb, SCAN_BLK>>>(N);
    scan_sums_kernel<<<1, 256>>>(nb);
    scan_add_kernel<<<(N + 1 + 255) / 256, 256>>>(N, E);
    csr_fill_kernel<<<(E + 255) / 256, 256>>>(E);

    // ---- h = x ----
    const int n4 = N * (C_DIM / 4);
    copy_f4_kernel<<<(n4 + 255) / 256, 256>>>((const float4*)x, (float4*)p_h, n4);

    // ---- B_l = w_ih @ W_l^T, then build fp16 concatenated weights ----
    gemm_nt_batched_kernel<<<dim3(6, 2, L), 256>>>(w_ih, w, p_bl, 384, C_DIM);
    {
        int total = L * WCAT_PER_L;
        build_wcat_kernel<<<(total + 255) / 256, 256>>>(p_bl, w_hh, total);
    }

    const int gx = (N + 63) / 64;
    const int agg_blocks = (N * 32 + 255) / 256;

    for (int l = 0; l < L; l++) {
        aggregate_csr_kernel<<<agg_blocks, 256>>>(p_h, p_agg, N);
        float* outp = (l == L - 1) ? (float*)d_out : nullptr;
        fused_layer_kernel<<<gx, 512, SM_TOT>>>(
            p_agg, p_h, p_wcat + (size_t)l * WCAT_PER_L,
            b_ih, b_hh, outp, N);
    }
}

// round 17
// speedup vs baseline: 1.1710x; 1.1710x over previous
#include <cuda_runtime.h>
#include <cuda_fp16.h>
#include <cstdint>
#include <cstddef>

// ---------------------------------------------------------------------------
// GatedGraphConv (10 layers) + GRUCell.
//  - Algebra: segment_sum linear => gi = aggH @ (w_ih@W_l^T)^T + b_ih
//  - fp16 split, precision-tiered:
//      n-path (in, hn): 2-term  A ~= Ah + Al   (error-critical, feeds tanh)
//      r/z gates:       1-term  A ~= Ah        (sigmoid gates, error-tolerant)
//  - r/z gates: K=256 concat GEMM  [agg|h] @ [B_g|W_g]^T.
//  - Per layer: CSR gather kernel, then ONE fused GEMM+GRU kernel (R13 base).
// ---------------------------------------------------------------------------

#define C_DIM 128
#define N_MAX 100352
#define E_MAX 1048576
#define L_MAX 16
#define WCAT_PER_L 98304   // 2*128*256 (r,z concat) + 2*128*128 (in, hn)

__device__ __align__(128) float g_h  [(size_t)N_MAX * C_DIM];
__device__ __align__(128) float g_agg[(size_t)N_MAX * C_DIM];
__device__ __align__(128) float g_bl [(size_t)L_MAX * 3 * C_DIM * C_DIM];
__device__ __align__(128) __half g_wcat[(size_t)L_MAX * WCAT_PER_L];
__device__ __align__(128) int g_src[E_MAX];
__device__ __align__(128) int g_dst[E_MAX];
__device__ __align__(128) int g_sorted_src[E_MAX];
__device__ __align__(128) int g_deg    [N_MAX];
__device__ __align__(128) int g_partial[N_MAX];
__device__ __align__(128) int g_rowptr [N_MAX + 1];
__device__ __align__(128) int g_cursor [N_MAX];
__device__ __align__(128) int g_bsums  [256];
__device__ int g_is64;

// ============================ helpers ======================================
__device__ __forceinline__ uint32_t smem_u32(const void* p) {
    uint32_t a;
    asm("{ .reg .u64 t; cvta.to.shared.u64 t, %1; cvt.u32.u64 %0, t; }" : "=r"(a) : "l"(p));
    return a;
}
__device__ __forceinline__ void ldmatrix_x4(uint32_t& r0, uint32_t& r1,
                                            uint32_t& r2, uint32_t& r3, uint32_t addr) {
    asm volatile("ldmatrix.sync.aligned.m8n8.x4.shared.b16 {%0,%1,%2,%3}, [%4];"
                 : "=r"(r0), "=r"(r1), "=r"(r2), "=r"(r3) : "r"(addr));
}
__device__ __forceinline__ void mma_fp16(float* d, const uint32_t* a, const uint32_t* b) {
    asm volatile(
        "mma.sync.aligned.m16n8k16.row.col.f32.f16.f16.f32 "
        "{%0,%1,%2,%3}, {%4,%5,%6,%7}, {%8,%9}, {%0,%1,%2,%3};"
        : "+f"(d[0]), "+f"(d[1]), "+f"(d[2]), "+f"(d[3])
        : "r"(a[0]), "r"(a[1]), "r"(a[2]), "r"(a[3]), "r"(b[0]), "r"(b[1]));
}
__device__ __forceinline__ float sigmoidf_(float x) { return 1.f / (1.f + __expf(-x)); }

// split float4 -> packed fp16 hi x4 and fp16 lo x4
__device__ __forceinline__ void split4h(float4 v, uint2& hi, uint2& lo) {
    __half hx = __float2half_rn(v.x), hy = __float2half_rn(v.y);
    __half hz = __float2half_rn(v.z), hw = __float2half_rn(v.w);
    __half ox = __float2half_rn(v.x - __half2float(hx));
    __half oy = __float2half_rn(v.y - __half2float(hy));
    __half oz = __float2half_rn(v.z - __half2float(hz));
    __half ow = __float2half_rn(v.w - __half2float(hw));
    hi.x = (uint32_t)__half_as_ushort(hx) | ((uint32_t)__half_as_ushort(hy) << 16);
    hi.y = (uint32_t)__half_as_ushort(hz) | ((uint32_t)__half_as_ushort(hw) << 16);
    lo.x = (uint32_t)__half_as_ushort(ox) | ((uint32_t)__half_as_ushort(oy) << 16);
    lo.y = (uint32_t)__half_as_ushort(oz) | ((uint32_t)__half_as_ushort(ow) << 16);
}

// ============================ prologue kernels =============================
__global__ void detect_edge_dtype_kernel(const int* __restrict__ e32, int nscan) {
    if (threadIdx.x == 0 && blockIdx.x == 0) {
        int acc = 0;
        for (int i = 1; i < nscan; i += 2) acc |= e32[i];
        g_is64 = (acc == 0) ? 1 : 0;
    }
}
__global__ void decode_edges_kernel(const int* __restrict__ e32, int E) {
    int i = blockIdx.x * blockDim.x + threadIdx.x;
    if (i >= E) return;
    if (g_is64) { g_src[i] = e32[2 * (size_t)i]; g_dst[i] = e32[2 * ((size_t)E + i)]; }
    else        { g_src[i] = e32[i];             g_dst[i] = e32[(size_t)E + i]; }
}
__global__ void copy_f4_kernel(const float4* __restrict__ s, float4* __restrict__ d, int n4) {
    int i = blockIdx.x * blockDim.x + threadIdx.x;
    if (i < n4) d[i] = s[i];
}

// wcat per layer: [0,65536): g in {r,z}: [c][k] k<128 -> Bl[g*128+c][k] else whh
//                 [65536,81920): in rows ; [81920,98304): hn rows
__global__ void build_wcat_kernel(const float* __restrict__ bl,
                                  const float* __restrict__ whh, int total) {
    int i = blockIdx.x * blockDim.x + threadIdx.x;
    if (i >= total) return;
    int l = i / WCAT_PER_L;
    int r = i - l * WCAT_PER_L;
    float v;
    if (r < 65536) {
        int g = r >> 15, rem = r & 32767, c = rem >> 8, k = rem & 255;
        int row = g * 128 + c;
        v = (k < 128) ? bl[(size_t)l * 49152 + row * 128 + k]
                      : whh[row * 128 + (k - 128)];
    } else {
        int r2 = r - 65536;
        int m = r2 >> 14, rem = r2 & 16383, c = rem >> 7, k = rem & 127;
        int row = 256 + c;
        v = m ? whh[row * 128 + k] : bl[(size_t)l * 49152 + row * 128 + k];
    }
    g_wcat[i] = __float2half_rn(v);
}

// ---- CSR build (once per call) ----
__global__ void zero_int_kernel(int* __restrict__ p, int n) {
    int i = blockIdx.x * blockDim.x + threadIdx.x;
    if (i < n) p[i] = 0;
}
__global__ void hist_kernel(int E) {
    int i = blockIdx.x * blockDim.x + threadIdx.x;
    if (i < E) atomicAdd(&g_deg[g_dst[i]], 1);
}
#define SCAN_BLK 1024
__global__ void scan_block_kernel(int N) {
    __shared__ int sh[SCAN_BLK];
    int tid = threadIdx.x;
    int gid = blockIdx.x * SCAN_BLK + tid;
    int v = (gid < N) ? g_deg[gid] : 0;
    sh[tid] = v; __syncthreads();
    for (int off = 1; off < SCAN_BLK; off <<= 1) {
        int t = (tid >= off) ? sh[tid - off] : 0;
        __syncthreads();
        sh[tid] += t;
        __syncthreads();
    }
    if (gid < N) g_partial[gid] = sh[tid] - v;
    if (tid == SCAN_BLK - 1) g_bsums[blockIdx.x] = sh[tid];
}
// parallel exclusive scan over block sums (nb <= 256)
__global__ void scan_sums_kernel(int nb) {
    __shared__ int sh[256];
    int tid = threadIdx.x;
    int v = (tid < nb) ? g_bsums[tid] : 0;
    sh[tid] = v; __syncthreads();
    for (int off = 1; off < 256; off <<= 1) {
        int t = (tid >= off) ? sh[tid - off] : 0;
        __syncthreads();
        sh[tid] += t;
        __syncthreads();
    }
    if (tid < nb) g_bsums[tid] = sh[tid] - v;
}
__global__ void scan_add_kernel(int N, int E) {
    int gid = blockIdx.x * blockDim.x + threadIdx.x;
    if (gid < N) {
        int v = g_partial[gid] + g_bsums[gid / SCAN_BLK];
        g_rowptr[gid] = v;
        g_cursor[gid] = v;
    }
    if (gid == N) g_rowptr[N] = E;
}
__global__ void csr_fill_kernel(int E) {
    int i = blockIdx.x * blockDim.x + threadIdx.x;
    if (i >= E) return;
    int pos = atomicAdd(&g_cursor[g_dst[i]], 1);
    g_sorted_src[pos] = g_src[i];
}

// ---- per-layer aggregation: warp per node, 2-way unrolled (R13-proven) ----
__global__ void aggregate_csr_kernel(const float* __restrict__ h,
                                     float* __restrict__ agg, int N)
{
    int t = blockIdx.x * blockDim.x + threadIdx.x;
    int node = t >> 5, lane = t & 31;
    if (node >= N) return;
    int e0 = g_rowptr[node], e1 = g_rowptr[node + 1];
    float4 acc0 = make_float4(0.f, 0.f, 0.f, 0.f);
    float4 acc1 = make_float4(0.f, 0.f, 0.f, 0.f);
    int e = e0;
    for (; e + 2 <= e1; e += 2) {
        int s0 = g_sorted_src[e];
        int s1 = g_sorted_src[e + 1];
        float4 v0 = __ldg(reinterpret_cast<const float4*>(h + (size_t)s0 * C_DIM) + lane);
        float4 v1 = __ldg(reinterpret_cast<const float4*>(h + (size_t)s1 * C_DIM) + lane);
        acc0.x += v0.x; acc0.y += v0.y; acc0.z += v0.z; acc0.w += v0.w;
        acc1.x += v1.x; acc1.y += v1.y; acc1.z += v1.z; acc1.w += v1.w;
    }
    if (e < e1) {
        int s0 = g_sorted_src[e];
        float4 v0 = __ldg(reinterpret_cast<const float4*>(h + (size_t)s0 * C_DIM) + lane);
        acc0.x += v0.x; acc0.y += v0.y; acc0.z += v0.z; acc0.w += v0.w;
    }
    acc0.x += acc1.x; acc0.y += acc1.y; acc0.z += acc1.z; acc0.w += acc1.w;
    *(reinterpret_cast<float4*>(agg + (size_t)node * C_DIM) + lane) = acc0;
}

// ================= SIMT NT GEMM (tiny B_l precompute, batched over z) ======
__global__ void __launch_bounds__(256) gemm_nt_batched_kernel(
    const float* __restrict__ A, const float* __restrict__ Wall,
    float* __restrict__ CoutAll, int M, int nout)
{
    __shared__ float As[64][68];
    __shared__ float Bs[64][68];
    const float* B = Wall + (size_t)blockIdx.z * C_DIM * C_DIM;
    float* Cout = CoutAll + (size_t)blockIdx.z * 3 * C_DIM * C_DIM;
    const int tid = threadIdx.x;
    const int row0 = blockIdx.x * 64, col0 = blockIdx.y * 64;
    const int tx = tid & 15, ty = tid >> 4;
    float acc[4][4];
#pragma unroll
    for (int i = 0; i < 4; i++)
#pragma unroll
        for (int j = 0; j < 4; j++) acc[i][j] = 0.f;
#pragma unroll
    for (int kt = 0; kt < 2; kt++) {
#pragma unroll
        for (int s = 0; s < 4; s++) {
            int i = tid + s * 256, r = i >> 4, c4 = i & 15;
            float4 va = make_float4(0.f, 0.f, 0.f, 0.f);
            if (row0 + r < M)
                va = *reinterpret_cast<const float4*>(A + (size_t)(row0 + r) * C_DIM + kt * 64 + c4 * 4);
            *reinterpret_cast<float4*>(&As[r][c4 * 4]) = va;
            float4 vb = *reinterpret_cast<const float4*>(B + (size_t)(col0 + r) * C_DIM + kt * 64 + c4 * 4);
            *reinterpret_cast<float4*>(&Bs[r][c4 * 4]) = vb;
        }
        __syncthreads();
#pragma unroll
        for (int k4 = 0; k4 < 16; k4++) {
            float4 a[4], b[4];
#pragma unroll
            for (int i = 0; i < 4; i++) a[i] = *reinterpret_cast<const float4*>(&As[ty * 4 + i][k4 * 4]);
#pragma unroll
            for (int j = 0; j < 4; j++) b[j] = *reinterpret_cast<const float4*>(&Bs[tx * 4 + j][k4 * 4]);
#pragma unroll
            for (int i = 0; i < 4; i++)
#pragma unroll
                for (int j = 0; j < 4; j++) {
                    acc[i][j] += a[i].x * b[j].x; acc[i][j] += a[i].y * b[j].y;
                    acc[i][j] += a[i].z * b[j].z; acc[i][j] += a[i].w * b[j].w;
                }
        }
        __syncthreads();
    }
#pragma unroll
    for (int i = 0; i < 4; i++) {
        int r = row0 + ty * 4 + i;
        if (r < M)
#pragma unroll
            for (int j = 0; j < 4; j++)
                Cout[(size_t)r * nout + col0 + tx * 4 + j] = acc[i][j];
    }
}

// ================== fused layer kernel (GEMMs + GRU) =======================
// R13 structure. CTA: 64 rows. A tile = [agg | h] 64 x 256 fp16, hi + lo.
// Phases: r (K=256, 1-TERM), z (K=256, 1-TERM), n (in+hn K=128 pair, 2-term).
#define A_LDA 528                       // 256 fp16 * 2 + 16B pad
#define A_TILE (64 * A_LDA)             // 33792
#define B_LDA_RZ 528
#define B_LDA_N  272
#define SM_AHI 0
#define SM_ALO A_TILE
#define SM_B   (2 * A_TILE)             // 67584
#define SM_TOT (2 * A_TILE + 69632)     // 137216

// 2-term phase: acc += (Ah + Al) @ B
__device__ __forceinline__ void phase2(uint32_t aH0, uint32_t aL0, uint32_t bB0,
                                       const int ksteps, float acc[2][2][4])
{
#pragma unroll
    for (int ks = 0; ks < ksteps; ks++) {
        const uint32_t koff = ks * 32;
        uint32_t aH[2][4], aL[2][4], bH[4];
#pragma unroll
        for (int im = 0; im < 2; im++) {
            ldmatrix_x4(aH[im][0], aH[im][1], aH[im][2], aH[im][3],
                        aH0 + (uint32_t)im * 16 * A_LDA + koff);
            ldmatrix_x4(aL[im][0], aL[im][1], aL[im][2], aL[im][3],
                        aL0 + (uint32_t)im * 16 * A_LDA + koff);
        }
        ldmatrix_x4(bH[0], bH[1], bH[2], bH[3], bB0 + koff);
#pragma unroll
        for (int im = 0; im < 2; im++)
#pragma unroll
            for (int in = 0; in < 2; in++) {
                mma_fp16(acc[im][in], aH[im], &bH[in * 2]);
                mma_fp16(acc[im][in], aL[im], &bH[in * 2]);
            }
    }
}

// 1-term phase: acc += Ah @ B   (r/z sigmoid gates -- error-tolerant)
__device__ __forceinline__ void phase1(uint32_t aH0, uint32_t bB0,
                                       const int ksteps, float acc[2][2][4])
{
#pragma unroll
    for (int ks = 0; ks < ksteps; ks++) {
        const uint32_t koff = ks * 32;
        uint32_t aH[2][4], bH[4];
#pragma unroll
        for (int im = 0; im < 2; im++) {
            ldmatrix_x4(aH[im][0], aH[im][1], aH[im][2], aH[im][3],
                        aH0 + (uint32_t)im * 16 * A_LDA + koff);
        }
        ldmatrix_x4(bH[0], bH[1], bH[2], bH[3], bB0 + koff);
#pragma unroll
        for (int im = 0; im < 2; im++)
#pragma unroll
            for (int in = 0; in < 2; in++) {
                mma_fp16(acc[im][in], aH[im], &bH[in * 2]);
            }
    }
}

__global__ void __launch_bounds__(512, 1)
fused_layer_kernel(const float* __restrict__ agg, float* __restrict__ h,
                   const __half* __restrict__ wl,
                   const float* __restrict__ b_ih, const float* __restrict__ b_hh,
                   float* __restrict__ out_relu, int M)
{
    extern __shared__ char smem[];
    const int tid  = threadIdx.x;
    const int wid  = tid >> 5;
    const int lane = tid & 31;
    const int row0 = blockIdx.x * 64;
    const int wm = wid & 1;
    const int wn = wid >> 1;

    // ---- build A tile: [agg | h] rows, fp16 hi/lo split ----
#pragma unroll
    for (int it = 0; it < 8; it++) {
        int idx = tid + it * 512;           // 0..4095 float4 over 64x256
        int row = idx >> 6;                 // 0..63
        int kk  = (idx & 63) * 4;           // 0..252
        bool ok = (row0 + row < M);
        float4 v = make_float4(0.f, 0.f, 0.f, 0.f);
        if (ok) {
            const float* srcp = (kk < 128)
                ? (agg + (size_t)(row0 + row) * C_DIM + kk)
                : (h   + (size_t)(row0 + row) * C_DIM + (kk - 128));
            v = *reinterpret_cast<const float4*>(srcp);
        }
        uint2 hi, lo;
        split4h(v, hi, lo);
        uint32_t off = (uint32_t)row * A_LDA + kk * 2;
        *reinterpret_cast<uint2*>(smem + SM_AHI + off) = hi;
        *reinterpret_cast<uint2*>(smem + SM_ALO + off) = lo;
    }

    // ---- fragment addressing ----
    const uint32_t sb = smem_u32(smem);
    const uint32_t a_off =
        (uint32_t)(wm * 32 + (lane & 15)) * A_LDA + (uint32_t)(lane >> 4) * 16;
    const uint32_t aH0 = sb + SM_AHI + a_off;
    const uint32_t aL0 = sb + SM_ALO + a_off;
    const uint32_t b_row = (uint32_t)(wn * 16 + ((lane >> 4) & 1) * 8 + (lane & 7));
    const uint32_t b_col = (uint32_t)((lane >> 3) & 1) * 16;
    const uint32_t bRZ = sb + SM_B + b_row * B_LDA_RZ + b_col;
    const uint32_t bN  = sb + SM_B + b_row * B_LDA_N  + b_col;

    float acc_r [2][2][4], acc_z [2][2][4], acc_in[2][2][4], acc_hn[2][2][4];
#pragma unroll
    for (int im = 0; im < 2; im++)
#pragma unroll
        for (int in = 0; in < 2; in++)
#pragma unroll
            for (int q = 0; q < 4; q++) {
                acc_r[im][in][q] = 0.f; acc_z[im][in][q] = 0.f;
                acc_in[im][in][q] = 0.f; acc_hn[im][in][q] = 0.f;
            }

    // ---- phase r: load wcat_rz[0] (128 x 256 fp16), K=256, 1-term ----
#pragma unroll
    for (int it = 0; it < 8; it++) {
        int idx = tid + it * 512;           // 0..4095 uint4
        int r = idx >> 5, c4 = idx & 31;
        uint4 v = *reinterpret_cast<const uint4*>(wl + (size_t)r * 256 + c4 * 8);
        *reinterpret_cast<uint4*>(smem + SM_B + (uint32_t)r * B_LDA_RZ + c4 * 16) = v;
    }
    __syncthreads();
    phase1(aH0, bRZ, 16, acc_r);
    __syncthreads();

    // ---- phase z: load wcat_rz[1], K=256, 1-term ----
#pragma unroll
    for (int it = 0; it < 8; it++) {
        int idx = tid + it * 512;
        int r = idx >> 5, c4 = idx & 31;
        uint4 v = *reinterpret_cast<const uint4*>(wl + 32768 + (size_t)r * 256 + c4 * 8);
        *reinterpret_cast<uint4*>(smem + SM_B + (uint32_t)r * B_LDA_RZ + c4 * 16) = v;
    }
    __syncthreads();
    phase1(aH0, bRZ, 16, acc_z);
    __syncthreads();

    // ---- phase n: load in (128x128) + hn (128x128) together, 2-term ----
#pragma unroll
    for (int it = 0; it < 8; it++) {
        int idx = tid + it * 512;           // 0..4095
        int m = idx >> 11, rem = idx & 2047;
        int r = rem >> 4, c4 = rem & 15;
        uint4 v = *reinterpret_cast<const uint4*>(wl + 65536 + m * 16384 + (size_t)r * 128 + c4 * 8);
        *reinterpret_cast<uint4*>(smem + SM_B + m * 34816 + (uint32_t)r * B_LDA_N + c4 * 16) = v;
    }
    __syncthreads();
    phase2(aH0,       aL0,       bN,         8, acc_in);   // agg half (K cols 0-127)
    phase2(aH0 + 256, aL0 + 256, bN + 34816, 8, acc_hn);   // h half  (K cols 128-255)

    // ---- epilogue: GRU, in-place h update ----
    const int row_l = lane >> 2;
    const int col_l = (lane & 3) * 2;
#pragma unroll
    for (int in = 0; in < 2; in++) {
        const int c = wn * 16 + in * 8 + col_l;
        const float bir0 = __ldg(b_ih + c),       bir1 = __ldg(b_ih + c + 1);
        const float bhr0 = __ldg(b_hh + c),       bhr1 = __ldg(b_hh + c + 1);
        const float biz0 = __ldg(b_ih + 128 + c), biz1 = __ldg(b_ih + 129 + c);
        const float bhz0 = __ldg(b_hh + 128 + c), bhz1 = __ldg(b_hh + 129 + c);
        const float bin0 = __ldg(b_ih + 256 + c), bin1 = __ldg(b_ih + 257 + c);
        const float bhn0 = __ldg(b_hh + 256 + c), bhn1 = __ldg(b_hh + 257 + c);
#pragma unroll
        for (int im = 0; im < 2; im++) {
#pragma unroll
            for (int q = 0; q < 2; q++) {
                int r = row0 + wm * 32 + im * 16 + q * 8 + row_l;
                if (r >= M) continue;
                float2 hold = *reinterpret_cast<const float2*>(h + (size_t)r * C_DIM + c);
                float rr0 = sigmoidf_(acc_r[im][in][q * 2 + 0] + bir0 + bhr0);
                float rr1 = sigmoidf_(acc_r[im][in][q * 2 + 1] + bir1 + bhr1);
                float zz0 = sigmoidf_(acc_z[im][in][q * 2 + 0] + biz0 + bhz0);
                float zz1 = sigmoidf_(acc_z[im][in][q * 2 + 1] + biz1 + bhz1);
                float nn0 = tanhf(acc_in[im][in][q * 2 + 0] + bin0 + rr0 * (acc_hn[im][in][q * 2 + 0] + bhn0));
                float nn1 = tanhf(acc_in[im][in][q * 2 + 1] + bin1 + rr1 * (acc_hn[im][in][q * 2 + 1] + bhn1));
                float h0 = (1.f - zz0) * nn0 + zz0 * hold.x;
                float h1 = (1.f - zz1) * nn1 + zz1 * hold.y;
                *reinterpret_cast<float2*>(h + (size_t)r * C_DIM + c) = make_float2(h0, h1);
                if (out_relu)
                    *reinterpret_cast<float2*>(out_relu + (size_t)r * C_DIM + c) =
                        make_float2(fmaxf(h0, 0.f), fmaxf(h1, 0.f));
            }
        }
    }
}

// ============================ launch =======================================
extern "C" void kernel_launch(void* const* d_in, const int* in_sizes, int n_in,
                              void* d_out, int out_size)
{
    const float* x    = (const float*)d_in[0];
    const int*   e32  = (const int*)  d_in[1];
    const float* w    = (const float*)d_in[2];
    const float* w_ih = (const float*)d_in[3];
    const float* w_hh = (const float*)d_in[4];
    const float* b_ih = (const float*)d_in[5];
    const float* b_hh = (const float*)d_in[6];

    const int N = in_sizes[0] / C_DIM;
    const int E = in_sizes[1] / 2;
    const int L = in_sizes[2] / (C_DIM * C_DIM);

    float *p_h, *p_agg, *p_bl;
    __half *p_wcat;
    cudaGetSymbolAddress((void**)&p_h,    g_h);
    cudaGetSymbolAddress((void**)&p_agg,  g_agg);
    cudaGetSymbolAddress((void**)&p_bl,   g_bl);
    cudaGetSymbolAddress((void**)&p_wcat, g_wcat);
    int *p_deg;
    cudaGetSymbolAddress((void**)&p_deg, g_deg);

    cudaFuncSetAttribute(fused_layer_kernel,
                         cudaFuncAttributeMaxDynamicSharedMemorySize, SM_TOT);

    // ---- edges + CSR (once) ----
    int nscan = 1024;
    if (2 * E < nscan) nscan = 2 * E;
    detect_edge_dtype_kernel<<<1, 32>>>(e32, nscan);
    decode_edges_kernel<<<(E + 255) / 256, 256>>>(e32, E);
    zero_int_kernel<<<(N + 255) / 256, 256>>>(p_deg, N);
    hist_kernel<<<(E + 255) / 256, 256>>>(E);
    const int nb = (N + SCAN_BLK - 1) / SCAN_BLK;
    scan_block_kernel<<<nb, SCAN_BLK>>>(N);
    scan_sums_kernel<<<1, 256>>>(nb);
    scan_add_kernel<<<(N + 1 + 255) / 256, 256>>>(N, E);
    csr_fill_kernel<<<(E + 255) / 256, 256>>>(E);

    // ---- h = x ----
    const int n4 = N * (C_DIM / 4);
    copy_f4_kernel<<<(n4 + 255) / 256, 256>>>((const float4*)x, (float4*)p_h, n4);

    // ---- B_l = w_ih @ W_l^T, then build fp16 concatenated weights ----
    gemm_nt_batched_kernel<<<dim3(6, 2, L), 256>>>(w_ih, w, p_bl, 384, C_DIM);
    {
        int total = L * WCAT_PER_L;
        build_wcat_kernel<<<(total + 255) / 256, 256>>>(p_bl, w_hh, total);
    }

    const int gx = (N + 63) / 64;
    const int agg_blocks = (N * 32 + 255) / 256;

    for (int l = 0; l < L; l++) {
        aggregate_csr_kernel<<<agg_blocks, 256>>>(p_h, p_agg, N);
        float* outp = (l == L - 1) ? (float*)d_out : nullptr;
        fused_layer_kernel<<<gx, 512, SM_TOT>>>(
            p_agg, p_h, p_wcat + (size_t)l * WCAT_PER_L,
            b_ih, b_hh, outp, N);
    }
}